// round 2
// baseline (speedup 1.0000x reference)
#include <cuda_runtime.h>

#define N_NODES 100000
#define N_EDGES 1600000
#define HID 128
#define NPB 32  // nodes per block in the fused GEMM

// Scratch (allocation-free rule: __device__ globals)
__device__ float g_h[N_NODES * HID];    // lifted features
__device__ float g_agg[N_NODES * HID];  // neighbor aggregation

// ---------------------------------------------------------------------------
// Kernel 1: lift  h = x @ W_lift + b_lift   (and zero agg, fused)
// ---------------------------------------------------------------------------
__global__ void lift_kernel(const float* __restrict__ x,
                            const float* __restrict__ W_lift,
                            const float* __restrict__ b_lift) {
    int idx = blockIdx.x * blockDim.x + threadIdx.x;
    if (idx >= N_NODES * HID) return;
    int n = idx >> 7;
    int f = idx & 127;
    float x0 = x[n * 3 + 0];
    float x1 = x[n * 3 + 1];
    float x2 = x[n * 3 + 2];
    float v = b_lift[f]
            + x0 * W_lift[0 * HID + f]
            + x1 * W_lift[1 * HID + f]
            + x2 * W_lift[2 * HID + f];
    g_h[idx] = v;
    g_agg[idx] = 0.0f;
}

// ---------------------------------------------------------------------------
// Kernel 2: scatter-add  agg[dst] += h[src]  over 1.6M edges
// edge_index is int32, [2, N_EDGES] row-major.
// one warp per edge; lane l handles features [4l, 4l+4) via vectorized red
// ---------------------------------------------------------------------------
__global__ void scatter_kernel(const int* __restrict__ ei) {
    int gtid = blockIdx.x * blockDim.x + threadIdx.x;
    int e = gtid >> 5;
    if (e >= N_EDGES) return;
    int lane = threadIdx.x & 31;

    unsigned int src = (unsigned int)ei[e];            // broadcast within warp
    unsigned int dst = (unsigned int)ei[N_EDGES + e];  // broadcast within warp
    if (src >= N_NODES || dst >= N_NODES) return;      // defensive guard

    const float4* hp = (const float4*)(g_h + (size_t)src * HID);
    float4 v = hp[lane];              // coalesced 512B per warp

    float* ap = g_agg + (size_t)dst * HID + lane * 4;
    asm volatile("red.global.add.v4.f32 [%0], {%1,%2,%3,%4};"
                 :: "l"(ap), "f"(v.x), "f"(v.y), "f"(v.z), "f"(v.w)
                 : "memory");
}

// ---------------------------------------------------------------------------
// Kernel 3: fused  out = tanh(agg@W_rel + b_rel + h@W_root) @ W_proj + b_proj
// 256 threads per block, 32 nodes per block.
// thread = (half, f): f in [0,128), half selects nodes half*16..half*16+15
// ---------------------------------------------------------------------------
__global__ void __launch_bounds__(256)
gnn_kernel(const float* __restrict__ W_rel,
           const float* __restrict__ b_rel,
           const float* __restrict__ W_root,
           const float* __restrict__ W_proj,
           const float* __restrict__ b_proj,
           float* __restrict__ out) {
    __shared__ float s_agg[NPB][HID];
    __shared__ float s_h[NPB][HID];
    __shared__ float s_part[NPB][4];

    int node0 = blockIdx.x * NPB;

    const float4* ga = (const float4*)(g_agg + (size_t)node0 * HID);
    const float4* gh = (const float4*)(g_h + (size_t)node0 * HID);
    float4* sa = (float4*)s_agg;
    float4* sh = (float4*)s_h;
#pragma unroll
    for (int i = 0; i < 4; i++) {
        sa[threadIdx.x + i * 256] = ga[threadIdx.x + i * 256];
        sh[threadIdx.x + i * 256] = gh[threadIdx.x + i * 256];
    }
    __syncthreads();

    int f = threadIdx.x & 127;
    int half = threadIdx.x >> 7;

    float acc[16];
    float brel = b_rel[f];
#pragma unroll
    for (int n = 0; n < 16; n++) acc[n] = brel;

#pragma unroll 4
    for (int k4 = 0; k4 < HID; k4 += 4) {
        float wr[4], wo[4];
#pragma unroll
        for (int j = 0; j < 4; j++) {
            wr[j] = W_rel[(k4 + j) * HID + f];   // coalesced row read, L1-hot
            wo[j] = W_root[(k4 + j) * HID + f];
        }
#pragma unroll
        for (int n = 0; n < 16; n++) {
            int node = half * 16 + n;
            float4 a  = *(const float4*)&s_agg[node][k4];  // LDS.128 broadcast
            float4 hv = *(const float4*)&s_h[node][k4];
            acc[n] += a.x * wr[0] + a.y * wr[1] + a.z * wr[2] + a.w * wr[3];
            acc[n] += hv.x * wo[0] + hv.y * wo[1] + hv.z * wo[2] + hv.w * wo[3];
        }
    }

    // tanh + projection: reduce over f (128 threads) per node
    float wp = W_proj[f];
    int wid = threadIdx.x >> 5;  // 0..7
#pragma unroll
    for (int n = 0; n < 16; n++) {
        float v = tanhf(acc[n]) * wp;
#pragma unroll
        for (int o = 16; o; o >>= 1) v += __shfl_xor_sync(0xffffffffu, v, o);
        if ((threadIdx.x & 31) == 0) s_part[half * 16 + n][wid & 3] = v;
    }
    __syncthreads();

    if (threadIdx.x < NPB) {
        float r = s_part[threadIdx.x][0] + s_part[threadIdx.x][1]
                + s_part[threadIdx.x][2] + s_part[threadIdx.x][3];
        out[node0 + threadIdx.x] = r + b_proj[0];
    }
}

// ---------------------------------------------------------------------------
// Launch
// inputs: 0:x 1:edge_index(int32!) 2:W_lift 3:b_lift 4:W_rel 5:b_rel
//         6:W_root 7:W_proj 8:b_proj
// ---------------------------------------------------------------------------
extern "C" void kernel_launch(void* const* d_in, const int* in_sizes, int n_in,
                              void* d_out, int out_size) {
    const float* x      = (const float*)d_in[0];
    const int*   ei     = (const int*)d_in[1];
    const float* W_lift = (const float*)d_in[2];
    const float* b_lift = (const float*)d_in[3];
    const float* W_rel  = (const float*)d_in[4];
    const float* b_rel  = (const float*)d_in[5];
    const float* W_root = (const float*)d_in[6];
    const float* W_proj = (const float*)d_in[7];
    const float* b_proj = (const float*)d_in[8];
    float* out = (float*)d_out;

    // 1. lift + zero agg
    lift_kernel<<<(N_NODES * HID + 255) / 256, 256>>>(x, W_lift, b_lift);

    // 2. scatter-add over edges (one warp per edge)
    scatter_kernel<<<(N_EDGES * 32) / 256, 256>>>(ei);

    // 3. fused matvecs + tanh + projection
    gnn_kernel<<<N_NODES / NPB, 256>>>(W_rel, b_rel, W_root, W_proj, b_proj, out);
}

// round 3
// speedup vs baseline: 10.5062x; 10.5062x over previous
#include <cuda_runtime.h>

#define N_NODES 100000
#define N_EDGES 1600000
#define HID 128

// Scratch (__device__ globals per allocation rules)
__device__ float4 g_x4[N_NODES];    // (x0, x1, x2, 1.0)
__device__ float4 g_agg4[N_NODES];  // (sum x0, sum x1, sum x2, deg)
__device__ float4 g_w1[HID];        // (B0,B1,B2,C): B = W_lift@W_rel, C = b_lift@W_rel
__device__ float4 g_w2[HID];        // (A0,A1,A2,D): A = W_lift@W_root, D = b_lift@W_root + b_rel
__device__ float  g_wp[HID];        // W_proj

// ---------------------------------------------------------------------------
// Kernel 0: precompute folded weight tables (1 block, 128 threads)
// ---------------------------------------------------------------------------
__global__ void prep_kernel(const float* __restrict__ W_lift,
                            const float* __restrict__ b_lift,
                            const float* __restrict__ W_rel,
                            const float* __restrict__ b_rel,
                            const float* __restrict__ W_root,
                            const float* __restrict__ W_proj) {
    int f = threadIdx.x;
    float a0 = 0.f, a1 = 0.f, a2 = 0.f, b0 = 0.f, b1 = 0.f, b2 = 0.f;
    float c = 0.f, d = 0.f;
#pragma unroll 8
    for (int k = 0; k < HID; k++) {
        float wr = W_rel[k * HID + f];
        float wo = W_root[k * HID + f];
        float l0 = W_lift[0 * HID + k];
        float l1 = W_lift[1 * HID + k];
        float l2 = W_lift[2 * HID + k];
        float bl = b_lift[k];
        b0 += l0 * wr; b1 += l1 * wr; b2 += l2 * wr; c += bl * wr;
        a0 += l0 * wo; a1 += l1 * wo; a2 += l2 * wo; d += bl * wo;
    }
    g_w1[f] = make_float4(b0, b1, b2, c);
    g_w2[f] = make_float4(a0, a1, a2, d + b_rel[f]);
    g_wp[f] = W_proj[f];
}

// ---------------------------------------------------------------------------
// Kernel 1: pack x into float4 (w=1.0 for degree counting) + zero agg
// ---------------------------------------------------------------------------
__global__ void pack_kernel(const float* __restrict__ x) {
    int n = blockIdx.x * blockDim.x + threadIdx.x;
    if (n >= N_NODES) return;
    g_x4[n] = make_float4(x[3 * n], x[3 * n + 1], x[3 * n + 2], 1.0f);
    g_agg4[n] = make_float4(0.f, 0.f, 0.f, 0.f);
}

// ---------------------------------------------------------------------------
// Kernel 2: scatter-add of (x, 1) — 16 bytes per edge, one thread per edge
// ---------------------------------------------------------------------------
__global__ void scatter_kernel(const int* __restrict__ ei) {
    int e = blockIdx.x * blockDim.x + threadIdx.x;
    if (e >= N_EDGES) return;
    unsigned int src = (unsigned int)ei[e];
    unsigned int dst = (unsigned int)ei[N_EDGES + e];
    if (src >= N_NODES || dst >= N_NODES) return;
    float4 v = g_x4[src];  // random 16B gather, 1.6MB working set (L2-resident)
    float* ap = (float*)&g_agg4[dst];
    asm volatile("red.global.add.v4.f32 [%0], {%1,%2,%3,%4};"
                 :: "l"(ap), "f"(v.x), "f"(v.y), "f"(v.z), "f"(v.w)
                 : "memory");
}

// ---------------------------------------------------------------------------
// Kernel 3: per-node  out[n] = sum_f tanh(dot4(agg4,w1_f)+dot4(x4,w2_f))*wp_f + b_proj
// one thread per node; weights staged in shared (uniform broadcast reads)
// ---------------------------------------------------------------------------
__global__ void __launch_bounds__(256)
final_kernel(const float* __restrict__ b_proj, float* __restrict__ out) {
    __shared__ float4 s_w1[HID];
    __shared__ float4 s_w2[HID];
    __shared__ float  s_wp[HID];
    if (threadIdx.x < HID) {
        s_w1[threadIdx.x] = g_w1[threadIdx.x];
        s_w2[threadIdx.x] = g_w2[threadIdx.x];
        s_wp[threadIdx.x] = g_wp[threadIdx.x];
    }
    __syncthreads();

    int n = blockIdx.x * blockDim.x + threadIdx.x;
    if (n >= N_NODES) return;

    float4 xv = g_x4[n];    // coalesced
    float4 av = g_agg4[n];  // coalesced

    float acc = 0.f;
#pragma unroll 8
    for (int f = 0; f < HID; f++) {
        float4 w1 = s_w1[f];  // uniform address -> smem broadcast
        float4 w2 = s_w2[f];
        float pre = av.x * w1.x + av.y * w1.y + av.z * w1.z + av.w * w1.w
                  + xv.x * w2.x + xv.y * w2.y + xv.z * w2.z + xv.w * w2.w;
        float t;
        asm("tanh.approx.f32 %0, %1;" : "=f"(t) : "f"(pre));
        acc += t * s_wp[f];
    }
    out[n] = acc + b_proj[0];
}

// ---------------------------------------------------------------------------
// Launch — inputs: 0:x 1:edge_index(int32) 2:W_lift 3:b_lift 4:W_rel 5:b_rel
//                  6:W_root 7:W_proj 8:b_proj
// ---------------------------------------------------------------------------
extern "C" void kernel_launch(void* const* d_in, const int* in_sizes, int n_in,
                              void* d_out, int out_size) {
    const float* x      = (const float*)d_in[0];
    const int*   ei     = (const int*)d_in[1];
    const float* W_lift = (const float*)d_in[2];
    const float* b_lift = (const float*)d_in[3];
    const float* W_rel  = (const float*)d_in[4];
    const float* b_rel  = (const float*)d_in[5];
    const float* W_root = (const float*)d_in[6];
    const float* W_proj = (const float*)d_in[7];
    const float* b_proj = (const float*)d_in[8];
    float* out = (float*)d_out;

    prep_kernel<<<1, HID>>>(W_lift, b_lift, W_rel, b_rel, W_root, W_proj);
    pack_kernel<<<(N_NODES + 255) / 256, 256>>>(x);
    scatter_kernel<<<(N_EDGES + 255) / 256, 256>>>(ei);
    final_kernel<<<(N_NODES + 255) / 256, 256>>>(b_proj, out);
}

// round 4
// speedup vs baseline: 12.3093x; 1.1716x over previous
#include <cuda_runtime.h>

#define N_NODES 100000
#define N_EDGES 1600000
#define HID 128

typedef unsigned long long u64;

// Scratch (__device__ globals per allocation rules)
__device__ float4 g_x4[N_NODES];    // (x0, x1, x2, 1.0)
__device__ float4 g_agg4[N_NODES];  // (sum x0, sum x1, sum x2, deg)
__device__ float4 g_w1[HID];        // (B0,B1,B2,C): B = W_lift@W_rel, C = b_lift@W_rel
__device__ float4 g_w2[HID];        // (A0,A1,A2,D): A = W_lift@W_root, D = b_lift@W_root + b_rel
__device__ float  g_wp[HID];        // W_proj

__device__ __forceinline__ u64 pk(float lo, float hi) {
    u64 r; asm("mov.b64 %0, {%1, %2};" : "=l"(r) : "f"(lo), "f"(hi)); return r;
}
__device__ __forceinline__ u64 pk1(float v) { return pk(v, v); }
#define FMA2(d, a, b, c) asm("fma.rn.f32x2 %0, %1, %2, %3;" : "=l"(d) : "l"(a), "l"(b), "l"(c))
#define UNPK(lo, hi, v)  asm("mov.b64 {%0, %1}, %2;" : "=f"(lo), "=f"(hi) : "l"(v))

// ---------------------------------------------------------------------------
// Kernel 1: block 0 = weight folding (prep), blocks 1.. = pack x + zero agg
// ---------------------------------------------------------------------------
__global__ void __launch_bounds__(256)
prep_pack_kernel(const float* __restrict__ x,
                 const float* __restrict__ W_lift,
                 const float* __restrict__ b_lift,
                 const float* __restrict__ W_rel,
                 const float* __restrict__ b_rel,
                 const float* __restrict__ W_root,
                 const float* __restrict__ W_proj) {
    if (blockIdx.x == 0) {
        __shared__ float red[8][HID];
        int f = threadIdx.x & 127;
        int ky = threadIdx.x >> 7;  // 0 or 1; each sums 64 k's
        float b0 = 0.f, b1 = 0.f, b2 = 0.f, c = 0.f;
        float a0 = 0.f, a1 = 0.f, a2 = 0.f, d = 0.f;
        int k0 = ky * 64;
#pragma unroll 8
        for (int k = k0; k < k0 + 64; k++) {
            float wr = W_rel[k * HID + f];
            float wo = W_root[k * HID + f];
            float l0 = W_lift[0 * HID + k];
            float l1 = W_lift[1 * HID + k];
            float l2 = W_lift[2 * HID + k];
            float bl = b_lift[k];
            b0 += l0 * wr; b1 += l1 * wr; b2 += l2 * wr; c += bl * wr;
            a0 += l0 * wo; a1 += l1 * wo; a2 += l2 * wo; d += bl * wo;
        }
        if (ky == 1) {
            red[0][f] = b0; red[1][f] = b1; red[2][f] = b2; red[3][f] = c;
            red[4][f] = a0; red[5][f] = a1; red[6][f] = a2; red[7][f] = d;
        }
        __syncthreads();
        if (ky == 0) {
            b0 += red[0][f]; b1 += red[1][f]; b2 += red[2][f]; c += red[3][f];
            a0 += red[4][f]; a1 += red[5][f]; a2 += red[6][f]; d += red[7][f];
            g_w1[f] = make_float4(b0, b1, b2, c);
            g_w2[f] = make_float4(a0, a1, a2, d + b_rel[f]);
            g_wp[f] = W_proj[f];
        }
    } else {
        int n = (blockIdx.x - 1) * 256 + threadIdx.x;
        if (n < N_NODES) {
            g_x4[n] = make_float4(x[3 * n], x[3 * n + 1], x[3 * n + 2], 1.0f);
            g_agg4[n] = make_float4(0.f, 0.f, 0.f, 0.f);
        }
    }
}

// ---------------------------------------------------------------------------
// Kernel 2: scatter-add of (x,1) — 2 edges per thread, int2 index loads
// ---------------------------------------------------------------------------
__global__ void scatter_kernel(const int* __restrict__ ei) {
    int t = blockIdx.x * blockDim.x + threadIdx.x;
    int e0 = t * 2;
    if (e0 >= N_EDGES) return;
    int2 s2 = *(const int2*)(ei + e0);            // src pair (8B aligned)
    int2 d2 = *(const int2*)(ei + N_EDGES + e0);  // dst pair

    unsigned int s0 = (unsigned int)s2.x, s1 = (unsigned int)s2.y;
    unsigned int q0 = (unsigned int)d2.x, q1 = (unsigned int)d2.y;

    // Issue both gathers before either red (MLP)
    float4 v0, v1;
    bool ok0 = (s0 < N_NODES) & (q0 < N_NODES);
    bool ok1 = (s1 < N_NODES) & (q1 < N_NODES);
    if (ok0) v0 = g_x4[s0];
    if (ok1) v1 = g_x4[s1];

    if (ok0) {
        float* ap = (float*)&g_agg4[q0];
        asm volatile("red.global.add.v4.f32 [%0], {%1,%2,%3,%4};"
                     :: "l"(ap), "f"(v0.x), "f"(v0.y), "f"(v0.z), "f"(v0.w) : "memory");
    }
    if (ok1) {
        float* ap = (float*)&g_agg4[q1];
        asm volatile("red.global.add.v4.f32 [%0], {%1,%2,%3,%4};"
                     :: "l"(ap), "f"(v1.x), "f"(v1.y), "f"(v1.z), "f"(v1.w) : "memory");
    }
}

// ---------------------------------------------------------------------------
// Kernel 3: out[n] = sum_f tanh(dot(agg4,w1_f)+dot(x4,w2_f)) * wp_f + b_proj
// f32x2 packed math over feature pairs; 2 nodes per thread.
// ---------------------------------------------------------------------------
__global__ void __launch_bounds__(256)
final_kernel(const float* __restrict__ b_proj, float* __restrict__ out) {
    __shared__ u64 sB0[64], sB1[64], sB2[64], sC[64];
    __shared__ u64 sA0[64], sA1[64], sA2[64], sD[64], sWP[64];
    if (threadIdx.x < 64) {
        int p = threadIdx.x;
        float4 u0 = g_w1[2 * p], u1 = g_w1[2 * p + 1];
        sB0[p] = pk(u0.x, u1.x); sB1[p] = pk(u0.y, u1.y);
        sB2[p] = pk(u0.z, u1.z); sC[p]  = pk(u0.w, u1.w);
        float4 v0 = g_w2[2 * p], v1 = g_w2[2 * p + 1];
        sA0[p] = pk(v0.x, v1.x); sA1[p] = pk(v0.y, v1.y);
        sA2[p] = pk(v0.z, v1.z); sD[p]  = pk(v0.w, v1.w);
        sWP[p] = pk(g_wp[2 * p], g_wp[2 * p + 1]);
    }
    __syncthreads();

    int n0 = (blockIdx.x * blockDim.x + threadIdx.x) * 2;
    if (n0 >= N_NODES) return;  // N_NODES even -> n0+1 always valid here

    float4 aA = g_agg4[n0], aB = g_agg4[n0 + 1];
    float4 xA = g_x4[n0],  xB = g_x4[n0 + 1];

    u64 axA = pk1(aA.x), ayA = pk1(aA.y), azA = pk1(aA.z), awA = pk1(aA.w);
    u64 xxA = pk1(xA.x), xyA = pk1(xA.y), xzA = pk1(xA.z);
    u64 axB = pk1(aB.x), ayB = pk1(aB.y), azB = pk1(aB.z), awB = pk1(aB.w);
    u64 xxB = pk1(xB.x), xyB = pk1(xB.y), xzB = pk1(xB.z);

    u64 accA = pk(0.f, 0.f), accB = pk(0.f, 0.f);

#pragma unroll 8
    for (int p = 0; p < 64; p++) {
        u64 B0 = sB0[p], B1 = sB1[p], B2 = sB2[p], C = sC[p];
        u64 A0 = sA0[p], A1 = sA1[p], A2 = sA2[p], D = sD[p];
        u64 WP = sWP[p];

        u64 pA = D, pB = D;
        FMA2(pA, axA, B0, pA); FMA2(pB, axB, B0, pB);
        FMA2(pA, ayA, B1, pA); FMA2(pB, ayB, B1, pB);
        FMA2(pA, azA, B2, pA); FMA2(pB, azB, B2, pB);
        FMA2(pA, awA, C,  pA); FMA2(pB, awB, C,  pB);
        FMA2(pA, xxA, A0, pA); FMA2(pB, xxB, A0, pB);
        FMA2(pA, xyA, A1, pA); FMA2(pB, xyB, A1, pB);
        FMA2(pA, xzA, A2, pA); FMA2(pB, xzB, A2, pB);

        float a0, a1, b0, b1;
        UNPK(a0, a1, pA); UNPK(b0, b1, pB);
        float t0, t1, t2, t3;
        asm("tanh.approx.f32 %0, %1;" : "=f"(t0) : "f"(a0));
        asm("tanh.approx.f32 %0, %1;" : "=f"(t1) : "f"(a1));
        asm("tanh.approx.f32 %0, %1;" : "=f"(t2) : "f"(b0));
        asm("tanh.approx.f32 %0, %1;" : "=f"(t3) : "f"(b1));
        u64 tA = pk(t0, t1), tB = pk(t2, t3);
        FMA2(accA, tA, WP, accA);
        FMA2(accB, tB, WP, accB);
    }

    float rA0, rA1, rB0, rB1;
    UNPK(rA0, rA1, accA); UNPK(rB0, rB1, accB);
    float bp = b_proj[0];
    out[n0]     = rA0 + rA1 + bp;
    out[n0 + 1] = rB0 + rB1 + bp;
}

// ---------------------------------------------------------------------------
// Launch — inputs: 0:x 1:edge_index(int32) 2:W_lift 3:b_lift 4:W_rel 5:b_rel
//                  6:W_root 7:W_proj 8:b_proj
// ---------------------------------------------------------------------------
extern "C" void kernel_launch(void* const* d_in, const int* in_sizes, int n_in,
                              void* d_out, int out_size) {
    const float* x      = (const float*)d_in[0];
    const int*   ei     = (const int*)d_in[1];
    const float* W_lift = (const float*)d_in[2];
    const float* b_lift = (const float*)d_in[3];
    const float* W_rel  = (const float*)d_in[4];
    const float* b_rel  = (const float*)d_in[5];
    const float* W_root = (const float*)d_in[6];
    const float* W_proj = (const float*)d_in[7];
    const float* b_proj = (const float*)d_in[8];
    float* out = (float*)d_out;

    prep_pack_kernel<<<1 + (N_NODES + 255) / 256, 256>>>(
        x, W_lift, b_lift, W_rel, b_rel, W_root, W_proj);
    scatter_kernel<<<(N_EDGES / 2 + 255) / 256, 256>>>(ei);
    final_kernel<<<(N_NODES / 2 + 255) / 256, 256>>>(b_proj, out);
}